// round 16
// baseline (speedup 1.0000x reference)
#include <cuda_runtime.h>

#define NB 8
#define T 16
#define C 256
#define CM 64
#define AA 32
#define HW 784
#define HWC (HW*C)        /* 200704 */
#define X4F (HWC/4)
#define NSPLIT 4
#define PS (HW/NSPLIT)    /* 196 */
#define SLOTS (NSPLIT*4)  /* 16 partial slots per frame */
#define NPART 512         /* partial blocks: 128 frames x 4 segments */
#define PPV 64            /* partial blocks per video */
#define JPV 17            /* branch jobs per video */
#define NBR (NB*JPV)      /* 136 branch blocks */

// Scratch (allocation-free rule: __device__ globals)
__device__ float    g_partial[NB*T*SLOTS*C];   // 2 MB
__device__ float    g_kern[NB*3*C];            // [b][k][c]
__device__ float    g_act[NB*T*C];             // [b][t][c]
__device__ unsigned g_pcnt[NB];                // monotone, mod PPV
__device__ unsigned g_bdone[NB];               // monotone, mod JPV
__device__ unsigned g_pflag[NB];               // set by 64th partial, reset by 17th brancher

// ---------------- Node 1: k_partial bodies + spin-gated branch blocks ------
// (EXACT R15 kernel — proven champion structure)
__global__ void __launch_bounds__(256) k_partial_branch(const float4* __restrict__ x4,
        const float* __restrict__ gw1, const float* __restrict__ ggam,
        const float* __restrict__ gbet, const float* __restrict__ gmean,
        const float* __restrict__ gvar, const float* __restrict__ gw2,
        const float* __restrict__ lw1, const float* __restrict__ lgam,
        const float* __restrict__ lbet, const float* __restrict__ lmean,
        const float* __restrict__ lvar, const float* __restrict__ lw2) {
    int bid = blockIdx.x, tid = threadIdx.x;

    if (bid < NPART) {
        int n = bid & 127, s = bid >> 7;       // preserves R2 issue order
        int c4 = tid & 63, pi = tid >> 6;
        const float4* xp = x4 + (size_t)n*X4F + (size_t)(s*PS + pi)*64 + c4;
        float4 a0 = make_float4(0,0,0,0), a1 = a0, a2 = a0, a3 = a0;
        #pragma unroll 4
        for (int i = 0; i < 48; i += 4) {
            float4 v0 = xp[(size_t)(i+0)*256];
            float4 v1 = xp[(size_t)(i+1)*256];
            float4 v2 = xp[(size_t)(i+2)*256];
            float4 v3 = xp[(size_t)(i+3)*256];
            a0.x+=v0.x; a0.y+=v0.y; a0.z+=v0.z; a0.w+=v0.w;
            a1.x+=v1.x; a1.y+=v1.y; a1.z+=v1.z; a1.w+=v1.w;
            a2.x+=v2.x; a2.y+=v2.y; a2.z+=v2.z; a2.w+=v2.w;
            a3.x+=v3.x; a3.y+=v3.y; a3.z+=v3.z; a3.w+=v3.w;
        }
        {   // 49th row per thread
            float4 v = xp[(size_t)48*256];
            a0.x+=v.x; a0.y+=v.y; a0.z+=v.z; a0.w+=v.w;
        }
        float4 r;
        r.x = (a0.x+a1.x)+(a2.x+a3.x);
        r.y = (a0.y+a1.y)+(a2.y+a3.y);
        r.z = (a0.z+a1.z)+(a2.z+a3.z);
        r.w = (a0.w+a1.w)+(a2.w+a3.w);
        ((float4*)g_partial)[(size_t)(n*SLOTS + s*4 + pi)*64 + c4] = r;
        __threadfence();
        __syncthreads();
        if (tid == 0) {
            int b = n >> 4;
            unsigned old = atomicAdd(&g_pcnt[b], 1u);
            if (((old + 1u) % (unsigned)PPV) == 0u)
                atomicExch(&g_pflag[b], 1u);   // release: video b partials visible
        }
        return;
    }

    // branch blocks: spin for their video, then exact R2 branch bodies
    int j = bid - NPART;                       // 0..135
    int b = j / JPV, r = j % JPV;
    if (tid == 0) {
        while (*(volatile unsigned*)&g_pflag[b] == 0u) __nanosleep(100);
    }
    __syncthreads();
    __threadfence();                           // acquire video b partials

    if (r < T) {
        int t = r;
        __shared__ float th_s[3*C];
        __shared__ float red[256];
        __shared__ float l_s[CM];
        #pragma unroll
        for (int dt = 0; dt < 3; dt++) {
            int tt = t + dt - 1;
            float s = 0.f;
            if (tt >= 0 && tt < T) {
                #pragma unroll
                for (int ss = 0; ss < SLOTS; ss++)
                    s += g_partial[(size_t)((b*T + tt)*SLOTS + ss)*C + tid];
                s *= (1.0f/(float)HW);
            }
            th_s[dt*C + tid] = s;
        }
        __syncthreads();
        int m = tid & 63, part = tid >> 6;
        float acc = 0.f;
        #pragma unroll 8
        for (int i = 0; i < 192; i++) {
            int jj = part*192 + i;             // jj = dt*256 + c
            acc += th_s[jj] * lw1[jj*CM + m];
        }
        red[tid] = acc;
        __syncthreads();
        if (tid < CM) {
            float v = red[tid] + red[tid+64] + red[tid+128] + red[tid+192];
            float inv = rsqrtf(lvar[tid] + 1e-3f);
            v = (v - lmean[tid]) * (lgam[tid] * inv) + lbet[tid];
            l_s[tid] = fmaxf(v, 0.f);
        }
        __syncthreads();
        float o = 0.f;
        #pragma unroll 8
        for (int mm = 0; mm < CM; mm++) o += l_s[mm] * lw2[mm*C + tid];
        g_act[(b*T + t)*C + tid] = 1.f/(1.f + expf(-o));
    } else {
        int c = tid;
        float th[T];
        #pragma unroll
        for (int t = 0; t < T; t++) {
            float s = 0.f;
            #pragma unroll
            for (int ss = 0; ss < SLOTS; ss++)
                s += g_partial[(size_t)((b*T + t)*SLOTS + ss)*C + c];
            th[t] = s * (1.0f/(float)HW);
        }
        float lg0 = 0.f, lg1 = 0.f, lg2 = 0.f;
        #pragma unroll 4
        for (int a = 0; a < AA; a++) {
            float g = 0.f;
            #pragma unroll
            for (int t = 0; t < T; t++) g += th[t] * gw1[t*AA + a];
            float inv = rsqrtf(gvar[a] + 1e-3f);
            g = (g - gmean[a]) * (ggam[a] * inv) + gbet[a];
            g = fmaxf(g, 0.f);
            lg0 += g * gw2[a*3 + 0];
            lg1 += g * gw2[a*3 + 1];
            lg2 += g * gw2[a*3 + 2];
        }
        float mx = fmaxf(lg0, fmaxf(lg1, lg2));
        float e0 = expf(lg0 - mx), e1 = expf(lg1 - mx), e2 = expf(lg2 - mx);
        float inv = 1.f/(e0 + e1 + e2);
        g_kern[(b*3 + 0)*C + c] = e0*inv;
        g_kern[(b*3 + 1)*C + c] = e1*inv;
        g_kern[(b*3 + 2)*C + c] = e2*inv;
    }
    __syncthreads();
    if (tid == 0) {
        unsigned old = atomicAdd(&g_bdone[b], 1u);
        if (((old + 1u) % (unsigned)JPV) == 0u)
            atomicExch(&g_pflag[b], 0u);       // reset for next replay
    }
}

// ---------------- Node 2: k_agg with 19KB smem (act+kern raw, fold in regs) -
// Same thread mapping, block geometry, x rotation and __stcs as the proven
// 30us kernel. Only change: smem holds raw act (16KB) + kern (3KB) instead of
// the folded 48KB coef table; the fold (c_k = kern_k * act) happens in the
// loop. smem 48->19KB lifts the occupancy cap from 4 to 5 CTAs/SM.
__global__ void __launch_bounds__(256, 5) k_agg(const float* __restrict__ x,
                                                float* __restrict__ y) {
    __shared__ float sm_act[T*C];    // 16 KB: [t][c]
    __shared__ float sm_kern[3*C];   //  3 KB: [k][c]
    int tid = threadIdx.x;
    int b  = (NB - 1) - blockIdx.y;
    int pb = (gridDim.x - 1) - blockIdx.x;
    int c4 = tid & 63, pi = tid >> 6;
    int p = pb*4 + pi;

    #pragma unroll
    for (int t = 0; t < T; t++)
        sm_act[t*C + tid] = g_act[(b*T + t)*C + tid];
    #pragma unroll
    for (int k = 0; k < 3; k++)
        sm_kern[k*C + tid] = g_kern[(b*3 + k)*C + tid];
    __syncthreads();

    const float4* sa = (const float4*)sm_act;
    const float4* sk = (const float4*)sm_kern;
    size_t base4 = ((size_t)(b*T)*HWC + (size_t)p*C) / 4 + c4;
    const float4* xp = (const float4*)x + base4;
    float4*       yp = (float4*)y + base4;
    const int S4 = X4F;
    float4 z = make_float4(0.f,0.f,0.f,0.f);
    float4 xm = z;
    float4 xc = xp[0];
    #pragma unroll
    for (int t = 0; t < T; t++) {
        float4 xn = (t < T-1) ? xp[(size_t)(t+1)*S4] : z;
        float4 ap = (t > 0)   ? sa[(t-1)*64 + c4] : z;
        float4 ac = sa[t*64 + c4];
        float4 an = (t < T-1) ? sa[(t+1)*64 + c4] : z;
        float4 k0 = sk[0*64 + c4];
        float4 k1 = sk[1*64 + c4];
        float4 k2 = sk[2*64 + c4];
        float4 o;
        o.x = (k0.x*ap.x)*xm.x + (k1.x*ac.x)*xc.x + (k2.x*an.x)*xn.x;
        o.y = (k0.y*ap.y)*xm.y + (k1.y*ac.y)*xc.y + (k2.y*an.y)*xn.y;
        o.z = (k0.z*ap.z)*xm.z + (k1.z*ac.z)*xc.z + (k2.z*an.z)*xn.z;
        o.w = (k0.w*ap.w)*xm.w + (k1.w*ac.w)*xc.w + (k2.w*an.w)*xn.w;
        __stcs(yp + (size_t)t*S4, o);
        xm = xc; xc = xn;
    }
}

extern "C" void kernel_launch(void* const* d_in, const int* in_sizes, int n_in,
                              void* d_out, int out_size) {
    const float* x       = (const float*)d_in[0];
    const float* gw1     = (const float*)d_in[1];
    const float* ggamma  = (const float*)d_in[2];
    const float* gbeta   = (const float*)d_in[3];
    const float* gmean   = (const float*)d_in[4];
    const float* gvar    = (const float*)d_in[5];
    const float* gw2     = (const float*)d_in[6];
    const float* lw1     = (const float*)d_in[7];
    const float* lgamma  = (const float*)d_in[8];
    const float* lbeta   = (const float*)d_in[9];
    const float* lmean   = (const float*)d_in[10];
    const float* lvar    = (const float*)d_in[11];
    const float* lw2     = (const float*)d_in[12];
    float* y = (float*)d_out;

    k_partial_branch<<<NPART + NBR, 256>>>((const float4*)x,
                                  gw1, ggamma, gbeta, gmean, gvar, gw2,
                                  lw1, lgamma, lbeta, lmean, lvar, lw2);
    k_agg<<<dim3(HW/4, NB), 256>>>(x, y);
}

// round 17
// speedup vs baseline: 1.0257x; 1.0257x over previous
#include <cuda_runtime.h>

#define NB 8
#define T 16
#define C 256
#define CM 64
#define AA 32
#define HW 784
#define HWC (HW*C)        /* 200704 */
#define X4F (HWC/4)
#define NSPLIT 4
#define PS (HW/NSPLIT)    /* 196 */
#define SLOTS (NSPLIT*4)  /* 16 partial slots per frame */
#define NPART 512         /* partial blocks: 128 frames x 4 segments */
#define PPV 64            /* partial blocks per video */
#define JPV 17            /* branch jobs per video */
#define NBR (NB*JPV)      /* 136 branch blocks */

// Scratch (allocation-free rule: __device__ globals)
__device__ float    g_partial[NB*T*SLOTS*C];   // 2 MB
__device__ float    g_kern[NB*3*C];            // [b][k][c]
__device__ float    g_act[NB*T*C];             // [b][t][c]
__device__ unsigned g_pcnt[NB];                // monotone, mod PPV
__device__ unsigned g_bdone[NB];               // monotone, mod JPV
__device__ unsigned g_pflag[NB];               // set by 64th partial, reset by 17th brancher

// ---------------- Node 1: k_partial bodies + spin-gated branch blocks ------
// (EXACT R15 champion kernel)
__global__ void __launch_bounds__(256) k_partial_branch(const float4* __restrict__ x4,
        const float* __restrict__ gw1, const float* __restrict__ ggam,
        const float* __restrict__ gbet, const float* __restrict__ gmean,
        const float* __restrict__ gvar, const float* __restrict__ gw2,
        const float* __restrict__ lw1, const float* __restrict__ lgam,
        const float* __restrict__ lbet, const float* __restrict__ lmean,
        const float* __restrict__ lvar, const float* __restrict__ lw2) {
    int bid = blockIdx.x, tid = threadIdx.x;

    if (bid < NPART) {
        int n = bid & 127, s = bid >> 7;       // preserves R2 issue order
        int c4 = tid & 63, pi = tid >> 6;
        const float4* xp = x4 + (size_t)n*X4F + (size_t)(s*PS + pi)*64 + c4;
        float4 a0 = make_float4(0,0,0,0), a1 = a0, a2 = a0, a3 = a0;
        #pragma unroll 4
        for (int i = 0; i < 48; i += 4) {
            float4 v0 = xp[(size_t)(i+0)*256];
            float4 v1 = xp[(size_t)(i+1)*256];
            float4 v2 = xp[(size_t)(i+2)*256];
            float4 v3 = xp[(size_t)(i+3)*256];
            a0.x+=v0.x; a0.y+=v0.y; a0.z+=v0.z; a0.w+=v0.w;
            a1.x+=v1.x; a1.y+=v1.y; a1.z+=v1.z; a1.w+=v1.w;
            a2.x+=v2.x; a2.y+=v2.y; a2.z+=v2.z; a2.w+=v2.w;
            a3.x+=v3.x; a3.y+=v3.y; a3.z+=v3.z; a3.w+=v3.w;
        }
        {   // 49th row per thread
            float4 v = xp[(size_t)48*256];
            a0.x+=v.x; a0.y+=v.y; a0.z+=v.z; a0.w+=v.w;
        }
        float4 r;
        r.x = (a0.x+a1.x)+(a2.x+a3.x);
        r.y = (a0.y+a1.y)+(a2.y+a3.y);
        r.z = (a0.z+a1.z)+(a2.z+a3.z);
        r.w = (a0.w+a1.w)+(a2.w+a3.w);
        ((float4*)g_partial)[(size_t)(n*SLOTS + s*4 + pi)*64 + c4] = r;
        __threadfence();
        __syncthreads();
        if (tid == 0) {
            int b = n >> 4;
            unsigned old = atomicAdd(&g_pcnt[b], 1u);
            if (((old + 1u) % (unsigned)PPV) == 0u)
                atomicExch(&g_pflag[b], 1u);   // release: video b partials visible
        }
        return;
    }

    // branch blocks: spin for their video, then exact branch bodies
    int j = bid - NPART;                       // 0..135
    int b = j / JPV, r = j % JPV;
    if (tid == 0) {
        while (*(volatile unsigned*)&g_pflag[b] == 0u) __nanosleep(100);
    }
    __syncthreads();
    __threadfence();                           // acquire video b partials

    if (r < T) {
        int t = r;
        __shared__ float th_s[3*C];
        __shared__ float red[256];
        __shared__ float l_s[CM];
        #pragma unroll
        for (int dt = 0; dt < 3; dt++) {
            int tt = t + dt - 1;
            float s = 0.f;
            if (tt >= 0 && tt < T) {
                #pragma unroll
                for (int ss = 0; ss < SLOTS; ss++)
                    s += g_partial[(size_t)((b*T + tt)*SLOTS + ss)*C + tid];
                s *= (1.0f/(float)HW);
            }
            th_s[dt*C + tid] = s;
        }
        __syncthreads();
        int m = tid & 63, part = tid >> 6;
        float acc = 0.f;
        #pragma unroll 8
        for (int i = 0; i < 192; i++) {
            int jj = part*192 + i;             // jj = dt*256 + c
            acc += th_s[jj] * lw1[jj*CM + m];
        }
        red[tid] = acc;
        __syncthreads();
        if (tid < CM) {
            float v = red[tid] + red[tid+64] + red[tid+128] + red[tid+192];
            float inv = rsqrtf(lvar[tid] + 1e-3f);
            v = (v - lmean[tid]) * (lgam[tid] * inv) + lbet[tid];
            l_s[tid] = fmaxf(v, 0.f);
        }
        __syncthreads();
        float o = 0.f;
        #pragma unroll 8
        for (int mm = 0; mm < CM; mm++) o += l_s[mm] * lw2[mm*C + tid];
        g_act[(b*T + t)*C + tid] = 1.f/(1.f + expf(-o));
    } else {
        int c = tid;
        float th[T];
        #pragma unroll
        for (int t = 0; t < T; t++) {
            float s = 0.f;
            #pragma unroll
            for (int ss = 0; ss < SLOTS; ss++)
                s += g_partial[(size_t)((b*T + t)*SLOTS + ss)*C + c];
            th[t] = s * (1.0f/(float)HW);
        }
        float lg0 = 0.f, lg1 = 0.f, lg2 = 0.f;
        #pragma unroll 4
        for (int a = 0; a < AA; a++) {
            float g = 0.f;
            #pragma unroll
            for (int t = 0; t < T; t++) g += th[t] * gw1[t*AA + a];
            float inv = rsqrtf(gvar[a] + 1e-3f);
            g = (g - gmean[a]) * (ggam[a] * inv) + gbet[a];
            g = fmaxf(g, 0.f);
            lg0 += g * gw2[a*3 + 0];
            lg1 += g * gw2[a*3 + 1];
            lg2 += g * gw2[a*3 + 2];
        }
        float mx = fmaxf(lg0, fmaxf(lg1, lg2));
        float e0 = expf(lg0 - mx), e1 = expf(lg1 - mx), e2 = expf(lg2 - mx);
        float inv = 1.f/(e0 + e1 + e2);
        g_kern[(b*3 + 0)*C + c] = e0*inv;
        g_kern[(b*3 + 1)*C + c] = e1*inv;
        g_kern[(b*3 + 2)*C + c] = e2*inv;
    }
    __syncthreads();
    if (tid == 0) {
        unsigned old = atomicAdd(&g_bdone[b], 1u);
        if (((old + 1u) % (unsigned)JPV) == 0u)
            atomicExch(&g_pflag[b], 0u);       // reset for next replay
    }
}

// ---------------- Node 2: champion k_agg + depth-2 load pipeline -----------
// Identical geometry to the proven 30us kernel (48KB folded coef table,
// 4 p-rows/block, c4=tid&63, reversed order, __stcs). ONLY change:
// x[t+2] is prefetched while computing t => two loads in flight per thread.
__global__ void k_agg(const float* __restrict__ x, float* __restrict__ y) {
    int tid = threadIdx.x;
    int b  = (NB - 1) - blockIdx.y;
    int pb = (gridDim.x - 1) - blockIdx.x;
    int c4 = tid & 63, pi = tid >> 6;
    int p = pb*4 + pi;
    __shared__ float coef[T*3*C];  // 48 KB
    float k0 = g_kern[(b*3 + 0)*C + tid];
    float k1 = g_kern[(b*3 + 1)*C + tid];
    float k2 = g_kern[(b*3 + 2)*C + tid];
    coef[(0*3 + 0)*C + tid]  = 0.f;
    coef[(15*3 + 2)*C + tid] = 0.f;
    #pragma unroll
    for (int ts = 0; ts < T; ts++) {
        float a = g_act[(b*T + ts)*C + tid];
        #pragma unroll
        for (int k = 0; k < 3; k++) {
            int t = ts + 1 - k;
            if (t >= 0 && t < T) {
                float kk = (k == 0) ? k0 : ((k == 1) ? k1 : k2);
                coef[(t*3 + k)*C + tid] = kk * a;
            }
        }
    }
    __syncthreads();
    const float4* cs4 = (const float4*)coef;
    size_t base4 = ((size_t)(b*T)*HWC + (size_t)p*C) / 4 + c4;
    const float4* xp = (const float4*)x + base4;
    float4*       yp = (float4*)y + base4;
    const int S4 = X4F;
    float4 z = make_float4(0.f,0.f,0.f,0.f);
    float4 xm = z;
    float4 xc = xp[0];
    float4 xn = xp[S4];                       // x[1]; T >= 2 always
    #pragma unroll
    for (int t = 0; t < T; t++) {
        float4 xn2 = (t < T-2) ? xp[(size_t)(t+2)*S4] : z;   // depth-2 prefetch
        float4 c0 = cs4[(t*3 + 0)*64 + c4];
        float4 c1 = cs4[(t*3 + 1)*64 + c4];
        float4 c2 = cs4[(t*3 + 2)*64 + c4];
        float4 o;
        o.x = c0.x*xm.x + c1.x*xc.x + c2.x*xn.x;
        o.y = c0.y*xm.y + c1.y*xc.y + c2.y*xn.y;
        o.z = c0.z*xm.z + c1.z*xc.z + c2.z*xn.z;
        o.w = c0.w*xm.w + c1.w*xc.w + c2.w*xn.w;
        __stcs(yp + (size_t)t*S4, o);
        xm = xc; xc = xn; xn = xn2;
    }
}

extern "C" void kernel_launch(void* const* d_in, const int* in_sizes, int n_in,
                              void* d_out, int out_size) {
    const float* x       = (const float*)d_in[0];
    const float* gw1     = (const float*)d_in[1];
    const float* ggamma  = (const float*)d_in[2];
    const float* gbeta   = (const float*)d_in[3];
    const float* gmean   = (const float*)d_in[4];
    const float* gvar    = (const float*)d_in[5];
    const float* gw2     = (const float*)d_in[6];
    const float* lw1     = (const float*)d_in[7];
    const float* lgamma  = (const float*)d_in[8];
    const float* lbeta   = (const float*)d_in[9];
    const float* lmean   = (const float*)d_in[10];
    const float* lvar    = (const float*)d_in[11];
    const float* lw2     = (const float*)d_in[12];
    float* y = (float*)d_out;

    k_partial_branch<<<NPART + NBR, 256>>>((const float4*)x,
                                  gw1, ggamma, gbeta, gmean, gvar, gw2,
                                  lw1, lgamma, lbeta, lmean, lvar, lw2);
    k_agg<<<dim3(HW/4, NB), 256>>>(x, y);
}